// round 6
// baseline (speedup 1.0000x reference)
#include <cuda_runtime.h>
#include <cuda_bf16.h>
#include <cstdint>

#define NN 2048
#define NROWS 16384
#define THREADS 512           // 16 warps = 2 rows, 8 warps per row
#define ROWS_PER_BLOCK 2

__device__ __align__(16) float g_cs[NN];
__device__ __align__(16) float g_sn[NN];

__global__ void rg_sincos_kernel(const float* __restrict__ angles) {
    int k = blockIdx.x * blockDim.x + threadIdx.x;
    if (k < NN) {
        float s, c;
        sincosf(angles[k], &s, &c);
        g_cs[k] = c;
        g_sn[k] = s;
    }
}

// 8 warps/row; lane owns two 4-element chunks (its own coalesced float4s).
// Carry flows from high k to low k. Chunk c covers k=4c..4c+3.
__global__ __launch_bounds__(THREADS, 2)
void rg_givens_kernel(const float* __restrict__ x, float* __restrict__ y) {
    __shared__ float smA[ROWS_PER_BLOCK][8];    // per-warp map A
    __shared__ float smB[ROWS_PER_BLOCK][8];    // per-warp map B
    __shared__ float smTop[ROWS_PER_BLOCK][8];  // per-warp top output (y[256(h+1)])
    __shared__ float smX[ROWS_PER_BLOCK][2];    // x0, x2047

    const int tid = threadIdx.x;
    const int l   = tid & 31;
    const int w   = tid >> 5;
    const int rib = w >> 3;          // row in block
    const int h   = w & 7;           // eighth of row
    const int row = blockIdx.x * ROWS_PER_BLOCK + rib;

    const float4* xr = (const float4*)(x + (size_t)row * NN);
    const float4* c4 = (const float4*)g_cs;
    const float4* s4 = (const float4*)g_sn;

    const int j0 = h * 64 + l;       // float4 index, chunk i=0 (k=256h+4l)
    const int j1 = j0 + 32;          // chunk i=1 (k=256h+128+4l)

    float4 xa = xr[j0], xb = xr[j1];
    float4 ca = c4[j0], cb = c4[j1];
    float4 sa = s4[j0], sb = s4[j1];

    if (h == 0 && l == 0)  smX[rib][0] = xa.x;   // x[0]
    if (h == 7 && l == 31) smX[rib][1] = xb.w;   // x[2047]
    __syncthreads();

    const float x0 = smX[rib][0];
    if (h == 0 && l == 0) {
        // x~[0] = w0 = s_2047*x_2047 + c_2047*x_0
        xa.x = fmaf(g_sn[NN - 1], smX[rib][1], g_cs[NN - 1] * x0);
    }

    // ---- per-chunk affine maps (t = 3..0 descending): carry' = A + B*carry ----
    float A0 = ca.w * xa.w;           float B0 = -sa.w;
    A0 = fmaf(-sa.z, A0, ca.z * xa.z); B0 *= -sa.z;
    A0 = fmaf(-sa.y, A0, ca.y * xa.y); B0 *= -sa.y;
    A0 = fmaf(-sa.x, A0, ca.x * xa.x); B0 *= -sa.x;

    float A1 = cb.w * xb.w;           float B1 = -sb.w;
    A1 = fmaf(-sb.z, A1, cb.z * xb.z); B1 *= -sb.z;
    A1 = fmaf(-sb.y, A1, cb.y * xb.y); B1 *= -sb.y;
    A1 = fmaf(-sb.x, A1, cb.x * xb.x); B1 *= -sb.x;

    // ---- two warp suffix scans (interleaved for ILP) ----
    float g0A = A0, g0B = B0, g1A = A1, g1B = B1;
    #pragma unroll
    for (int d = 1; d < 32; d <<= 1) {
        float a0 = __shfl_down_sync(0xffffffffu, g0A, d);
        float b0 = __shfl_down_sync(0xffffffffu, g0B, d);
        float a1 = __shfl_down_sync(0xffffffffu, g1A, d);
        float b1 = __shfl_down_sync(0xffffffffu, g1B, d);
        if (l + d < 32) {
            g0A = fmaf(g0B, a0, g0A); g0B *= b0;
            g1A = fmaf(g1B, a1, g1A); g1B *= b1;
        }
    }
    float n0A = __shfl_down_sync(0xffffffffu, g0A, 1);
    float n0B = __shfl_down_sync(0xffffffffu, g0B, 1);
    float n1A = __shfl_down_sync(0xffffffffu, g1A, 1);
    float n1B = __shfl_down_sync(0xffffffffu, g1B, 1);
    float G1A = __shfl_sync(0xffffffffu, g1A, 0);   // total map of i=1 group
    float G1B = __shfl_sync(0xffffffffu, g1B, 0);

    // warp total map W = G0 ∘ G1; publish
    if (l == 0) {
        smA[rib][h] = fmaf(g0B, g1A, g0A);
        smB[rib][h] = g0B * g1B;
    }
    __syncthreads();

    // carry entering this warp = W7∘...∘W_{h+1} applied top-down to x0
    float cinw = x0;
    #pragma unroll
    for (int j = 7; j >= 1; j--) {
        if (j > h) cinw = fmaf(smB[rib][j], cinw, smA[rib][j]);
    }

    // per-lane entering carries
    float cr1 = (l == 31) ? cinw : fmaf(n1B, cinw, n1A);
    float cin0 = fmaf(G1B, cinw, G1A);
    float cr0 = (l == 31) ? cin0 : fmaf(n0B, cin0, n0A);

    // ---- replay (t = 3..0); out_t = y[k_t+1] ----
    float t1o3 = fmaf(cb.w, cr1, sb.w * xb.w); cr1 = fmaf(-sb.w, cr1, cb.w * xb.w);
    float t1o2 = fmaf(cb.z, cr1, sb.z * xb.z); cr1 = fmaf(-sb.z, cr1, cb.z * xb.z);
    float t1o1 = fmaf(cb.y, cr1, sb.y * xb.y); cr1 = fmaf(-sb.y, cr1, cb.y * xb.y);
    float t1o0 = fmaf(cb.x, cr1, sb.x * xb.x); cr1 = fmaf(-sb.x, cr1, cb.x * xb.x);

    float t0o3 = fmaf(ca.w, cr0, sa.w * xa.w); cr0 = fmaf(-sa.w, cr0, ca.w * xa.w);
    float t0o2 = fmaf(ca.z, cr0, sa.z * xa.z); cr0 = fmaf(-sa.z, cr0, ca.z * xa.z);
    float t0o1 = fmaf(ca.y, cr0, sa.y * xa.y); cr0 = fmaf(-sa.y, cr0, ca.y * xa.y);
    float t0o0 = fmaf(ca.x, cr0, sa.x * xa.x); cr0 = fmaf(-sa.x, cr0, ca.x * xa.x);

    // ---- boundary exchange: chunk c's float4 leads with y[4c] from chunk c-1 ----
    float up0   = __shfl_up_sync(0xffffffffu, t0o3, 1);
    float up1   = __shfl_up_sync(0xffffffffu, t1o3, 1);
    float t0l31 = __shfl_sync(0xffffffffu, t0o3, 31);
    if (l == 31) smTop[rib][h] = t1o3;      // y[256(h+1)] for next warp
    __syncthreads();

    float recv1 = (l == 0) ? t0l31 : up1;
    float recv0;
    if (l == 0) {
        recv0 = (h == 0) ? cr0              // y[0] = global exit carry
                         : smTop[rib][h - 1];
    } else {
        recv0 = up0;
    }

    // ---- coalesced aligned stores ----
    float4* yr = (float4*)(y + (size_t)row * NN);
    yr[j0] = make_float4(recv0, t0o0, t0o1, t0o2);
    yr[j1] = make_float4(recv1, t1o0, t1o1, t1o2);
}

extern "C" void kernel_launch(void* const* d_in, const int* in_sizes, int n_in,
                              void* d_out, int out_size) {
    const float* x      = (const float*)d_in[0];   // [16384, 2048] fp32
    const float* angles = (const float*)d_in[1];   // [2048] fp32
    float* y = (float*)d_out;                      // [16384, 2048] fp32

    (void)in_sizes; (void)n_in; (void)out_size;

    rg_sincos_kernel<<<(NN + 255) / 256, 256>>>(angles);
    rg_givens_kernel<<<NROWS / ROWS_PER_BLOCK, THREADS>>>(x, y);
}